// round 3
// baseline (speedup 1.0000x reference)
#include <cuda_runtime.h>

#define NN 100000      // nodes
#define EE 1000000     // edges
#define HD 64          // hidden
#define GG 512         // graphs
#define EPS_GEN 1e-7f
#define EPS_BN  1e-5f

// ---------------- scratch (device globals; no allocations) ----------------
__device__ float g_h [NN * HD];
__device__ float g_h2[NN * HD];
__device__ float g_m [NN * HD];
__device__ float g_vt[GG * HD];
__device__ float g_vn[GG * HD];
__device__ float g_sum[HD];      // node-BN sum
__device__ float g_sq [HD];      // node-BN sumsq
__device__ float g_vnsA[2 * HD]; // vn-BN1 sum|sumsq
__device__ float g_vnsB[2 * HD]; // vn-BN2 sum|sumsq
__device__ float g_cnt[GG];

// ---------------- init: cnt=0, vt=0, vn=vn0 ----------------
__global__ void k_init(const float* __restrict__ vn0) {
    int i = blockIdx.x * blockDim.x + threadIdx.x;
    if (i < GG) g_cnt[i] = 0.f;
    if (i < GG * HD) {
        g_vn[i] = vn0[i & 63];
        g_vt[i] = 0.f;
    }
}

// ---------------- node counts per graph (run-length, batch sorted) -------
__global__ void k_cnt(const int* __restrict__ batch) {
    int t = blockIdx.x * blockDim.x + threadIdx.x;
    int base = t * 32;
    if (base >= NN) return;
    int end = min(base + 32, NN);
    int cur = batch[base];
    float acc = 0.f;
    for (int r = base; r < end; r++) {
        int b = batch[r];
        if (b != cur) { atomicAdd(&g_cnt[cur], acc); cur = b; acc = 0.f; }
        acc += 1.f;
    }
    atomicAdd(&g_cnt[cur], acc);
}

// ---------------- atom encoder: h = sum_f atom_table[x+off] + vn0 --------
__global__ void k_atom(const float4* __restrict__ atab,
                       const int* __restrict__ x,
                       const float4* __restrict__ vn0) {
    int t = blockIdx.x * blockDim.x + threadIdx.x;
    int n = t >> 4, lane = t & 15;
    if (n >= NN) return;
    const int aoff[9] = {0, 119, 124, 136, 148, 158, 164, 170, 172};
    float4 a = __ldg(&vn0[lane]);
#pragma unroll
    for (int i = 0; i < 9; i++) {
        int idx = __ldg(&x[n * 9 + i]) + aoff[i];
        float4 v = __ldg(&atab[idx * 16 + lane]);
        a.x += v.x; a.y += v.y; a.z += v.z; a.w += v.w;
    }
    ((float4*)g_h)[n * 16 + lane] = a;
}

// ---------------- prep0: zero m + node stats ----------------
__global__ void k_prep0() {
    int t = blockIdx.x * blockDim.x + threadIdx.x;
    int stride = gridDim.x * blockDim.x;
    for (int i = t; i < NN * HD; i += stride) g_m[i] = 0.f;
    if (t < HD) { g_sum[t] = 0.f; g_sq[t] = 0.f; }
}

// ---------------- edge scatter: m[dst] += relu(h[src]+bond_emb)+eps ------
__global__ void __launch_bounds__(256) k_scatter(int use_h2,
                                                 const int* __restrict__ ei,
                                                 const int* __restrict__ ea,
                                                 const float4* __restrict__ btab) {
    int t = blockIdx.x * 256 + threadIdx.x;
    int e = t >> 4, lane = t & 15;
    if (e >= EE) return;
    const float* hsrc = use_h2 ? g_h2 : g_h;
    int src = __ldg(&ei[e]);
    int dst = __ldg(&ei[EE + e]);
    int a0 = __ldg(&ea[e * 3 + 0]);
    int a1 = __ldg(&ea[e * 3 + 1]);
    int a2 = __ldg(&ea[e * 3 + 2]);
    float4 b0 = __ldg(&btab[a0 * 16 + lane]);          // BOND_OFF[0]=0
    float4 b1 = __ldg(&btab[(5 + a1) * 16 + lane]);    // BOND_OFF[1]=5
    float4 b2 = __ldg(&btab[(11 + a2) * 16 + lane]);   // BOND_OFF[2]=11
    float4 hv = __ldg((const float4*)hsrc + src * 16 + lane);
    float4 msg;
    msg.x = fmaxf(hv.x + b0.x + b1.x + b2.x, 0.f) + EPS_GEN;
    msg.y = fmaxf(hv.y + b0.y + b1.y + b2.y, 0.f) + EPS_GEN;
    msg.z = fmaxf(hv.z + b0.z + b1.z + b2.z, 0.f) + EPS_GEN;
    msg.w = fmaxf(hv.w + b0.w + b1.w + b2.w, 0.f) + EPS_GEN;
    float* p = g_m + (size_t)dst * 64 + lane * 4;
    asm volatile("red.global.add.v4.f32 [%0], {%1,%2,%3,%4};"
                 :: "l"(p), "f"(msg.x), "f"(msg.y), "f"(msg.z), "f"(msg.w)
                 : "memory");
}

// ---------------- (h_in + m) @ W + b (+res) -> g_h ; fused BN stats ------
__global__ void __launch_bounds__(256) k_matmul(int layer0,
                                                const float* __restrict__ W,
                                                const float* __restrict__ bias) {
    __shared__ __align__(16) float W_sh[64 * 64];
    __shared__ float in_sh[64][65];
    __shared__ float s_sum[64], s_sq[64];
    int tid = threadIdx.x;
    int base = blockIdx.x * 64;
    const float* hin = layer0 ? g_h : g_h2;
    // load W (16 KB) via float4
    {
        const float4* W4 = (const float4*)W;
        float4* Ws4 = (float4*)W_sh;
#pragma unroll
        for (int i = 0; i < 4; i++) Ws4[tid + i * 256] = __ldg(&W4[tid + i * 256]);
    }
    // load in = h_in + m (64 rows)
#pragma unroll
    for (int i = 0; i < 16; i++) {
        int idx = tid + i * 256;
        int r = idx >> 6, f = idx & 63;
        int row = base + r;
        float v = 0.f;
        if (row < NN) v = hin[row * 64 + f] + g_m[row * 64 + f];
        in_sh[r][f] = v;
    }
    if (tid < 64) { s_sum[tid] = 0.f; s_sq[tid] = 0.f; }
    __syncthreads();

    int ng = tid >> 4, cg = tid & 15;   // 4 nodes x 4 cols per thread
    float acc[4][4];
#pragma unroll
    for (int i = 0; i < 4; i++)
#pragma unroll
        for (int j = 0; j < 4; j++) acc[i][j] = 0.f;
#pragma unroll 8
    for (int k = 0; k < 64; k++) {
        float4 w = *(const float4*)&W_sh[k * 64 + cg * 4];
#pragma unroll
        for (int i = 0; i < 4; i++) {
            float iv = in_sh[ng * 4 + i][k];
            acc[i][0] = fmaf(iv, w.x, acc[i][0]);
            acc[i][1] = fmaf(iv, w.y, acc[i][1]);
            acc[i][2] = fmaf(iv, w.z, acc[i][2]);
            acc[i][3] = fmaf(iv, w.w, acc[i][3]);
        }
    }
    float4 bv = __ldg((const float4*)bias + cg);
    float csum[4] = {0, 0, 0, 0}, csq[4] = {0, 0, 0, 0};
#pragma unroll
    for (int i = 0; i < 4; i++) {
        int row = base + ng * 4 + i;
        if (row < NN) {
            float4 o;
            o.x = acc[i][0] + bv.x; o.y = acc[i][1] + bv.y;
            o.z = acc[i][2] + bv.z; o.w = acc[i][3] + bv.w;
            if (!layer0) {  // residual: + old h
                float4 r = *((const float4*)g_h + row * 16 + cg);
                o.x += r.x; o.y += r.y; o.z += r.z; o.w += r.w;
            }
            *((float4*)g_h + row * 16 + cg) = o;
            csum[0] += o.x; csq[0] += o.x * o.x;
            csum[1] += o.y; csq[1] += o.y * o.y;
            csum[2] += o.z; csq[2] += o.z * o.z;
            csum[3] += o.w; csq[3] += o.w * o.w;
        }
    }
#pragma unroll
    for (int j = 0; j < 4; j++) {
        atomicAdd(&s_sum[cg * 4 + j], csum[j]);
        atomicAdd(&s_sq [cg * 4 + j], csq[j]);
    }
    __syncthreads();
    if (tid < 64) {
        atomicAdd(&g_sum[tid], s_sum[tid]);
        atomicAdd(&g_sq [tid], s_sq[tid]);
    }
}

// ---- h2 = relu(BN(h)); zero m rows; pool h2 -> vt; zero vn stats --------
__global__ void __launch_bounds__(256) k_bn_apply(const float* __restrict__ gamma,
                                                  const float* __restrict__ beta,
                                                  const int* __restrict__ batch) {
    int tid = threadIdx.x;
    int f = tid & 63;
    float mu = g_sum[f] * (1.f / NN);
    float var = g_sq[f] * (1.f / NN) - mu * mu;
    float ga = gamma[f] * rsqrtf(var + EPS_BN);
    float sh = beta[f] - mu * ga;
    if (blockIdx.x == 0 && tid < 128) { g_vnsA[tid] = 0.f; g_vnsB[tid] = 0.f; }
    int r0 = blockIdx.x * 1024 + (tid >> 6);
    int rend = min(blockIdx.x * 1024 + 1024, NN);
    int cur = -1;
    float acc = 0.f;
    for (int r = r0; r < rend; r += 4) {
        float h = g_h[r * 64 + f];
        float v = fmaxf(fmaf(h, ga, sh), 0.f);
        g_h2[r * 64 + f] = v;
        g_m[r * 64 + f] = 0.f;
        int b = __ldg(&batch[r]);
        if (b != cur) {
            if (cur >= 0) atomicAdd(&g_vt[cur * 64 + f], acc);
            cur = b; acc = v;
        } else acc += v;
    }
    if (cur >= 0) atomicAdd(&g_vt[cur * 64 + f], acc);
}

// ---- virtual node step A: y = (vt + vn) @ W1 + b1 ; stats -> vnsA -------
__global__ void k_vn_a(const float* __restrict__ W1, const float* __restrict__ b1) {
    __shared__ float row[64];
    int g = blockIdx.x, j = threadIdx.x;
    row[j] = g_vt[g * 64 + j] + g_vn[g * 64 + j];
    __syncthreads();
    float acc = __ldg(&b1[j]);
#pragma unroll
    for (int k = 0; k < 64; k++) acc = fmaf(row[k], __ldg(&W1[k * 64 + j]), acc);
    g_vt[g * 64 + j] = acc;
    atomicAdd(&g_vnsA[j], acc);
    atomicAdd(&g_vnsA[64 + j], acc * acc);
}

// ---- vn step B: z = relu(BN1(y)); y2 = z @ W2 + b2 ; stats -> vnsB ------
__global__ void k_vn_b(const float* __restrict__ g1, const float* __restrict__ be1,
                       const float* __restrict__ W2, const float* __restrict__ b2) {
    __shared__ float z[64];
    int g = blockIdx.x, j = threadIdx.x;
    float mu = g_vnsA[j] * (1.f / GG);
    float var = g_vnsA[64 + j] * (1.f / GG) - mu * mu;
    float ga = __ldg(&g1[j]) * rsqrtf(var + EPS_BN);
    float y = g_vt[g * 64 + j];
    z[j] = fmaxf((y - mu) * ga + __ldg(&be1[j]), 0.f);
    __syncthreads();
    float acc = __ldg(&b2[j]);
#pragma unroll
    for (int k = 0; k < 64; k++) acc = fmaf(z[k], __ldg(&W2[k * 64 + j]), acc);
    g_vt[g * 64 + j] = acc;
    atomicAdd(&g_vnsB[j], acc);
    atomicAdd(&g_vnsB[64 + j], acc * acc);
}

// ---- vn step C: vn = relu(BN2(y2)) ----------------------------------
__global__ void k_vn_c(const float* __restrict__ g2, const float* __restrict__ be2) {
    int i = blockIdx.x * blockDim.x + threadIdx.x;
    if (i >= GG * HD) return;
    int j = i & 63;
    float mu = g_vnsB[j] * (1.f / GG);
    float var = g_vnsB[64 + j] * (1.f / GG) - mu * mu;
    float ga = __ldg(&g2[j]) * rsqrtf(var + EPS_BN);
    g_vn[i] = fmaxf((g_vt[i] - mu) * ga + __ldg(&be2[j]), 0.f);
}

// ---- h2 += vn[batch]; zero node stats + vt ------------------------------
__global__ void __launch_bounds__(256) k_add_vn(const int* __restrict__ batch) {
    int idx = blockIdx.x * 256 + threadIdx.x;
    if (blockIdx.x == 0 && threadIdx.x < 64) {
        g_sum[threadIdx.x] = 0.f;
        g_sq[threadIdx.x] = 0.f;
    }
    if (blockIdx.x == 1) {
        for (int i = threadIdx.x; i < GG * HD; i += 256) g_vt[i] = 0.f;
    }
    if (idx < NN * HD) {
        int n = idx >> 6;
        int b = __ldg(&batch[n]);
        g_h2[idx] += g_vn[b * 64 + (idx & 63)];
    }
}

// ---- pool: vt[g] = segment_sum(h) ---------------------------------------
__global__ void __launch_bounds__(256) k_pool(const int* __restrict__ batch) {
    int tid = threadIdx.x;
    int f = tid & 63;
    int r0 = blockIdx.x * 1024 + (tid >> 6);
    int rend = min(blockIdx.x * 1024 + 1024, NN);
    int cur = -1;
    float acc = 0.f;
    for (int r = r0; r < rend; r += 4) {
        float v = g_h[r * 64 + f];
        int b = __ldg(&batch[r]);
        if (b != cur) {
            if (cur >= 0) atomicAdd(&g_vt[cur * 64 + f], acc);
            cur = b; acc = v;
        } else acc += v;
    }
    if (cur >= 0) atomicAdd(&g_vt[cur * 64 + f], acc);
}

// ---- out = (vt/clip(cnt,1) - mu)*rstd*gamma + beta ----------------------
__global__ void k_final(float* __restrict__ out,
                        const float* __restrict__ gamma,
                        const float* __restrict__ beta) {
    int i = blockIdx.x * blockDim.x + threadIdx.x;
    if (i >= GG * HD) return;
    int g = i >> 6, f = i & 63;
    float mu = g_sum[f] * (1.f / NN);
    float var = g_sq[f] * (1.f / NN) - mu * mu;
    float rstd = rsqrtf(var + EPS_BN);
    float c = fmaxf(g_cnt[g], 1.f);
    out[i] = (g_vt[i] / c - mu) * rstd * __ldg(&gamma[f]) + __ldg(&beta[f]);
}

// =========================================================================
extern "C" void kernel_launch(void* const* d_in, const int* in_sizes, int n_in,
                              void* d_out, int out_size) {
    const float* atab  = (const float*)d_in[0];
    const float* btab  = (const float*)d_in[1];
    const float* vn0   = (const float*)d_in[2];
    const float* gcnW  = (const float*)d_in[3];
    const float* gcnb  = (const float*)d_in[4];
    const float* ngam  = (const float*)d_in[5];
    const float* nbet  = (const float*)d_in[6];
    const float* vnW1  = (const float*)d_in[7];
    const float* vnb1  = (const float*)d_in[8];
    const float* vng1  = (const float*)d_in[9];
    const float* vnbe1 = (const float*)d_in[10];
    const float* vnW2  = (const float*)d_in[11];
    const float* vnb2  = (const float*)d_in[12];
    const float* vng2  = (const float*)d_in[13];
    const float* vnbe2 = (const float*)d_in[14];
    const int*   x     = (const int*)d_in[15];
    const int*   ei    = (const int*)d_in[16];
    const int*   ea    = (const int*)d_in[17];
    const int*   batch = (const int*)d_in[18];
    float* out = (float*)d_out;

    const int MM_BLOCKS = (NN + 63) / 64;        // 1563
    const int BN_BLOCKS = (NN + 1023) / 1024;    // 98
    const int SC_BLOCKS = EE / 16;               // 62500
    const int AV_BLOCKS = (NN * HD + 255) / 256; // 25000

    // init
    k_init<<<(GG * HD + 255) / 256, 256>>>(vn0);
    k_cnt<<<(NN + 32 * 256 - 1) / (32 * 256), 256>>>(batch);
    k_atom<<<(NN * 16 + 255) / 256, 256>>>((const float4*)atab, x, (const float4*)vn0);
    k_prep0<<<2048, 256>>>();

    // layer 0: conv only (input h, no residual)
    k_scatter<<<SC_BLOCKS, 256>>>(0, ei, ea, (const float4*)btab);
    k_matmul<<<MM_BLOCKS, 256>>>(1, gcnW, gcnb);

    // layers 1..6: BN->ReLU->vnode->conv->+res
    for (int l = 1; l < 7; l++) {
        int li = l - 1;
        k_bn_apply<<<BN_BLOCKS, 256>>>(ngam + li * 64, nbet + li * 64, batch);
        k_vn_a<<<GG, 64>>>(vnW1 + li * 4096, vnb1 + li * 64);
        k_vn_b<<<GG, 64>>>(vng1 + li * 64, vnbe1 + li * 64,
                           vnW2 + li * 4096, vnb2 + li * 64);
        k_vn_c<<<(GG * HD + 255) / 256, 256>>>(vng2 + li * 64, vnbe2 + li * 64);
        k_add_vn<<<AV_BLOCKS, 256>>>(batch);
        k_scatter<<<SC_BLOCKS, 256>>>(1, ei, ea, (const float4*)btab);
        k_matmul<<<MM_BLOCKS, 256>>>(0, gcnW + l * 4096, gcnb + l * 64);
    }

    // readout: BN(h) then mean pool (BN is affine -> apply to pooled mean)
    k_pool<<<BN_BLOCKS, 256>>>(batch);
    k_final<<<(GG * HD + 255) / 256, 256>>>(out, ngam + 6 * 64, nbet + 6 * 64);
}

// round 9
// speedup vs baseline: 1.1427x; 1.1427x over previous
#include <cuda_runtime.h>

#define NN 100000      // nodes
#define EE 1000000     // edges
#define HD 64          // hidden
#define GG 512         // graphs
#define EPS_GEN 1e-7f
#define EPS_BN  1e-5f

// ---------------- scratch (device globals; no allocations) ----------------
__device__ float g_h [NN * HD];
__device__ float g_h2[NN * HD];
__device__ float g_m [NN * HD];   // conv input: h_in + aggregated messages
__device__ float g_vt[GG * HD];
__device__ float g_vn[GG * HD];
__device__ float g_sum[HD];
__device__ float g_sq [HD];
__device__ float g_vnsA[2 * HD];
__device__ float g_vnsB[2 * HD];
__device__ float g_cnt[GG];
// CSR by destination
__device__ int g_deg[NN];
__device__ int g_rowptr[NN];
__device__ int g_cur[NN];
__device__ int g_bsum[128];
__device__ int g_boff[128];
__device__ unsigned g_epk[EE];    // packed: src | a0<<17 | a1<<20 | a2<<23

// ---------------- init: deg=0, cnt=0, vt=0, vn=vn0, stats=0 ---------------
__global__ void k_init(const float* __restrict__ vn0) {
    int i = blockIdx.x * blockDim.x + threadIdx.x;
    int stride = gridDim.x * blockDim.x;
    for (int j = i; j < NN; j += stride) g_deg[j] = 0;
    if (i < GG) g_cnt[i] = 0.f;
    if (i < GG * HD) { g_vn[i] = vn0[i & 63]; g_vt[i] = 0.f; }
    if (i < HD) { g_sum[i] = 0.f; g_sq[i] = 0.f; }
}

// ---------------- node counts per graph (run-length, batch sorted) --------
__global__ void k_cnt(const int* __restrict__ batch) {
    int t = blockIdx.x * blockDim.x + threadIdx.x;
    int base = t * 32;
    if (base >= NN) return;
    int end = min(base + 32, NN);
    int cur = batch[base];
    float acc = 0.f;
    for (int r = base; r < end; r++) {
        int b = batch[r];
        if (b != cur) { atomicAdd(&g_cnt[cur], acc); cur = b; acc = 0.f; }
        acc += 1.f;
    }
    atomicAdd(&g_cnt[cur], acc);
}

// ---------------- atom encoder: h = sum_f atom_table[x+off] + vn0 ---------
__global__ void k_atom(const float4* __restrict__ atab,
                       const int* __restrict__ x,
                       const float4* __restrict__ vn0) {
    int t = blockIdx.x * blockDim.x + threadIdx.x;
    int n = t >> 4, lane = t & 15;
    if (n >= NN) return;
    const int aoff[9] = {0, 119, 124, 136, 148, 158, 164, 170, 172};
    float4 a = __ldg(&vn0[lane]);
#pragma unroll
    for (int i = 0; i < 9; i++) {
        int idx = __ldg(&x[n * 9 + i]) + aoff[i];
        float4 v = __ldg(&atab[idx * 16 + lane]);
        a.x += v.x; a.y += v.y; a.z += v.z; a.w += v.w;
    }
    ((float4*)g_h)[n * 16 + lane] = a;
}

// ================= CSR build (per call; edges static within call) =========
__global__ void k_hist(const int* __restrict__ ei) {
    int e = blockIdx.x * 256 + threadIdx.x;
    if (e >= EE) return;
    atomicAdd(&g_deg[__ldg(&ei[EE + e])], 1);
}

__global__ void k_scan1() {   // 98 blocks x 1024: chunk sums
    __shared__ int ws[32];
    int b = blockIdx.x, tid = threadIdx.x;
    int i = b * 1024 + tid;
    int v = (i < NN) ? g_deg[i] : 0;
    int s = v;
#pragma unroll
    for (int o = 16; o; o >>= 1) s += __shfl_down_sync(~0u, s, o);
    if ((tid & 31) == 0) ws[tid >> 5] = s;
    __syncthreads();
    if (tid < 32) {
        int t = ws[tid];
#pragma unroll
        for (int o = 16; o; o >>= 1) t += __shfl_down_sync(~0u, t, o);
        if (tid == 0) g_bsum[b] = t;
    }
}

__global__ void k_scan2() {   // 1 block x 128: exclusive scan of chunk sums
    __shared__ int sm[128];
    int tid = threadIdx.x;
    int nb = (NN + 1023) / 1024;                 // 98
    int v = (tid < nb) ? g_bsum[tid] : 0;
    sm[tid] = v; __syncthreads();
    for (int o = 1; o < 128; o <<= 1) {
        int t = (tid >= o) ? sm[tid - o] : 0;
        __syncthreads();
        sm[tid] += t;
        __syncthreads();
    }
    g_boff[tid] = sm[tid] - v;
}

__global__ void k_scan3() {   // 98 blocks x 1024: rowptr + cursor
    __shared__ int sm[1024];
    int b = blockIdx.x, tid = threadIdx.x;
    int i = b * 1024 + tid;
    int v = (i < NN) ? g_deg[i] : 0;
    sm[tid] = v; __syncthreads();
    for (int o = 1; o < 1024; o <<= 1) {
        int t = (tid >= o) ? sm[tid - o] : 0;
        __syncthreads();
        sm[tid] += t;
        __syncthreads();
    }
    if (i < NN) {
        int r = g_boff[b] + sm[tid] - v;   // exclusive
        g_rowptr[i] = r;
        g_cur[i] = r;
    }
}

__global__ void k_fill(const int* __restrict__ ei, const int* __restrict__ ea) {
    int e = blockIdx.x * 256 + threadIdx.x;
    if (e >= EE) return;
    int dst = __ldg(&ei[EE + e]);
    int p = atomicAdd(&g_cur[dst], 1);
    unsigned pk = (unsigned)__ldg(&ei[e])
                | ((unsigned)__ldg(&ea[e * 3 + 0]) << 17)
                | ((unsigned)__ldg(&ea[e * 3 + 1]) << 20)
                | ((unsigned)__ldg(&ea[e * 3 + 2]) << 23);
    g_epk[p] = pk;
}

// ====== gather: g_m[n] = hin[n] + sum_e relu(hin[src]+bond_emb)+eps =======
#define GATHER_BLOCKS 4096
__global__ void __launch_bounds__(256) k_gather(int use_h2,
                                                const float2* __restrict__ btab2) {
    __shared__ float2 comb[60 * 32];   // combined bond table, 15KB
    int tid = threadIdx.x;
    for (int i = tid; i < 60 * 32; i += 256) {
        int c = i >> 5, f = i & 31;
        int a0 = c % 5, t = c / 5, a1 = t % 6, a2 = t / 6;
        float2 v0 = __ldg(&btab2[a0 * 32 + f]);
        float2 v1 = __ldg(&btab2[(5 + a1) * 32 + f]);
        float2 v2 = __ldg(&btab2[(11 + a2) * 32 + f]);
        comb[i] = make_float2(v0.x + v1.x + v2.x, v0.y + v1.y + v2.y);
    }
    __syncthreads();

    const float2* __restrict__ hin =
        use_h2 ? (const float2*)g_h2 : (const float2*)g_h;

    int lane = tid & 31;
    const int GW = GATHER_BLOCKS * 8;
    for (int n = blockIdx.x * 8 + (tid >> 5); n < NN; n += GW) {
        int start = __ldg(&g_rowptr[n]);
        int deg = __ldg(&g_deg[n]);
        float2 acc = __ldg(&hin[n * 32 + lane]);
        int j = 0;
        for (; j + 4 <= deg; j += 4) {
            unsigned pk[4];
            float2 hv[4];
#pragma unroll
            for (int t = 0; t < 4; t++) pk[t] = __ldg(&g_epk[start + j + t]);
#pragma unroll
            for (int t = 0; t < 4; t++) {
                int src = pk[t] & 0x1FFFF;
                hv[t] = __ldg(&hin[src * 32 + lane]);
            }
#pragma unroll
            for (int t = 0; t < 4; t++) {
                int c = ((pk[t] >> 17) & 7) + 5 * ((pk[t] >> 20) & 7) + 30 * ((pk[t] >> 23) & 1);
                float2 e = comb[c * 32 + lane];
                acc.x += fmaxf(hv[t].x + e.x, 0.f) + EPS_GEN;
                acc.y += fmaxf(hv[t].y + e.y, 0.f) + EPS_GEN;
            }
        }
        for (; j < deg; j++) {
            unsigned p = __ldg(&g_epk[start + j]);
            int src = p & 0x1FFFF;
            int c = ((p >> 17) & 7) + 5 * ((p >> 20) & 7) + 30 * ((p >> 23) & 1);
            float2 h = __ldg(&hin[src * 32 + lane]);
            float2 e = comb[c * 32 + lane];
            acc.x += fmaxf(h.x + e.x, 0.f) + EPS_GEN;
            acc.y += fmaxf(h.y + e.y, 0.f) + EPS_GEN;
        }
        ((float2*)g_m)[n * 32 + lane] = acc;
    }
}

// ---------------- g_m @ W + b (+res) -> g_h ; fused BN stats --------------
__global__ void __launch_bounds__(256) k_matmul(int layer0,
                                                const float* __restrict__ W,
                                                const float* __restrict__ bias) {
    __shared__ __align__(16) float W_sh[64 * 64];
    __shared__ float in_sh[64][65];
    __shared__ float s_sum[64], s_sq[64];
    int tid = threadIdx.x;
    int base = blockIdx.x * 64;
    {
        const float4* W4 = (const float4*)W;
        float4* Ws4 = (float4*)W_sh;
#pragma unroll
        for (int i = 0; i < 4; i++) Ws4[tid + i * 256] = __ldg(&W4[tid + i * 256]);
    }
#pragma unroll
    for (int i = 0; i < 16; i++) {
        int idx = tid + i * 256;
        int r = idx >> 6, f = idx & 63;
        int row = base + r;
        in_sh[r][f] = (row < NN) ? g_m[row * 64 + f] : 0.f;
    }
    if (tid < 64) { s_sum[tid] = 0.f; s_sq[tid] = 0.f; }
    __syncthreads();

    int ng = tid >> 4, cg = tid & 15;
    float acc[4][4];
#pragma unroll
    for (int i = 0; i < 4; i++)
#pragma unroll
        for (int j = 0; j < 4; j++) acc[i][j] = 0.f;
#pragma unroll 8
    for (int k = 0; k < 64; k++) {
        float4 w = *(const float4*)&W_sh[k * 64 + cg * 4];
#pragma unroll
        for (int i = 0; i < 4; i++) {
            float iv = in_sh[ng * 4 + i][k];
            acc[i][0] = fmaf(iv, w.x, acc[i][0]);
            acc[i][1] = fmaf(iv, w.y, acc[i][1]);
            acc[i][2] = fmaf(iv, w.z, acc[i][2]);
            acc[i][3] = fmaf(iv, w.w, acc[i][3]);
        }
    }
    float4 bv = __ldg((const float4*)bias + cg);
    float csum[4] = {0, 0, 0, 0}, csq[4] = {0, 0, 0, 0};
#pragma unroll
    for (int i = 0; i < 4; i++) {
        int row = base + ng * 4 + i;
        if (row < NN) {
            float4 o;
            o.x = acc[i][0] + bv.x; o.y = acc[i][1] + bv.y;
            o.z = acc[i][2] + bv.z; o.w = acc[i][3] + bv.w;
            if (!layer0) {
                float4 r = *((const float4*)g_h + row * 16 + cg);
                o.x += r.x; o.y += r.y; o.z += r.z; o.w += r.w;
            }
            *((float4*)g_h + row * 16 + cg) = o;
            csum[0] += o.x; csq[0] += o.x * o.x;
            csum[1] += o.y; csq[1] += o.y * o.y;
            csum[2] += o.z; csq[2] += o.z * o.z;
            csum[3] += o.w; csq[3] += o.w * o.w;
        }
    }
#pragma unroll
    for (int j = 0; j < 4; j++) {
        atomicAdd(&s_sum[cg * 4 + j], csum[j]);
        atomicAdd(&s_sq [cg * 4 + j], csq[j]);
    }
    __syncthreads();
    if (tid < 64) {
        atomicAdd(&g_sum[tid], s_sum[tid]);
        atomicAdd(&g_sq [tid], s_sq[tid]);
    }
}

// ---- h2 = relu(BN(h)); pool h2 -> vt; zero vn stats ----------------------
__global__ void __launch_bounds__(256) k_bn_apply(const float* __restrict__ gamma,
                                                  const float* __restrict__ beta,
                                                  const int* __restrict__ batch) {
    int tid = threadIdx.x;
    int f = tid & 63;
    float mu = g_sum[f] * (1.f / NN);
    float var = g_sq[f] * (1.f / NN) - mu * mu;
    float ga = gamma[f] * rsqrtf(var + EPS_BN);
    float sh = beta[f] - mu * ga;
    if (blockIdx.x == 0 && tid < 128) { g_vnsA[tid] = 0.f; g_vnsB[tid] = 0.f; }
    int r0 = blockIdx.x * 1024 + (tid >> 6);
    int rend = min(blockIdx.x * 1024 + 1024, NN);
    int cur = -1;
    float acc = 0.f;
    for (int r = r0; r < rend; r += 4) {
        float h = g_h[r * 64 + f];
        float v = fmaxf(fmaf(h, ga, sh), 0.f);
        g_h2[r * 64 + f] = v;
        int b = __ldg(&batch[r]);
        if (b != cur) {
            if (cur >= 0) atomicAdd(&g_vt[cur * 64 + f], acc);
            cur = b; acc = v;
        } else acc += v;
    }
    if (cur >= 0) atomicAdd(&g_vt[cur * 64 + f], acc);
}

// ---- virtual node MLP ----------------------------------------------------
__global__ void k_vn_a(const float* __restrict__ W1, const float* __restrict__ b1) {
    __shared__ float row[64];
    int g = blockIdx.x, j = threadIdx.x;
    row[j] = g_vt[g * 64 + j] + g_vn[g * 64 + j];
    __syncthreads();
    float acc = __ldg(&b1[j]);
#pragma unroll
    for (int k = 0; k < 64; k++) acc = fmaf(row[k], __ldg(&W1[k * 64 + j]), acc);
    g_vt[g * 64 + j] = acc;
    atomicAdd(&g_vnsA[j], acc);
    atomicAdd(&g_vnsA[64 + j], acc * acc);
}

__global__ void k_vn_b(const float* __restrict__ g1, const float* __restrict__ be1,
                       const float* __restrict__ W2, const float* __restrict__ b2) {
    __shared__ float z[64];
    int g = blockIdx.x, j = threadIdx.x;
    float mu = g_vnsA[j] * (1.f / GG);
    float var = g_vnsA[64 + j] * (1.f / GG) - mu * mu;
    float ga = __ldg(&g1[j]) * rsqrtf(var + EPS_BN);
    float y = g_vt[g * 64 + j];
    z[j] = fmaxf((y - mu) * ga + __ldg(&be1[j]), 0.f);
    __syncthreads();
    float acc = __ldg(&b2[j]);
#pragma unroll
    for (int k = 0; k < 64; k++) acc = fmaf(z[k], __ldg(&W2[k * 64 + j]), acc);
    g_vt[g * 64 + j] = acc;
    atomicAdd(&g_vnsB[j], acc);
    atomicAdd(&g_vnsB[64 + j], acc * acc);
}

__global__ void k_vn_c(const float* __restrict__ g2, const float* __restrict__ be2) {
    int i = blockIdx.x * blockDim.x + threadIdx.x;
    if (i >= GG * HD) return;
    int j = i & 63;
    float mu = g_vnsB[j] * (1.f / GG);
    float var = g_vnsB[64 + j] * (1.f / GG) - mu * mu;
    float ga = __ldg(&g2[j]) * rsqrtf(var + EPS_BN);
    g_vn[i] = fmaxf((g_vt[i] - mu) * ga + __ldg(&be2[j]), 0.f);
}

// ---- h2 += vn[batch]; zero node stats + vt -------------------------------
__global__ void __launch_bounds__(256) k_add_vn(const int* __restrict__ batch) {
    int idx = blockIdx.x * 256 + threadIdx.x;
    if (blockIdx.x == 0 && threadIdx.x < 64) {
        g_sum[threadIdx.x] = 0.f;
        g_sq[threadIdx.x] = 0.f;
    }
    if (blockIdx.x == 1) {
        for (int i = threadIdx.x; i < GG * HD; i += 256) g_vt[i] = 0.f;
    }
    if (idx < NN * HD) {
        int n = idx >> 6;
        int b = __ldg(&batch[n]);
        g_h2[idx] += g_vn[b * 64 + (idx & 63)];
    }
}

// ---- pool: vt[g] = segment_sum(h) ----------------------------------------
__global__ void __launch_bounds__(256) k_pool(const int* __restrict__ batch) {
    int tid = threadIdx.x;
    int f = tid & 63;
    int r0 = blockIdx.x * 1024 + (tid >> 6);
    int rend = min(blockIdx.x * 1024 + 1024, NN);
    int cur = -1;
    float acc = 0.f;
    for (int r = r0; r < rend; r += 4) {
        float v = g_h[r * 64 + f];
        int b = __ldg(&batch[r]);
        if (b != cur) {
            if (cur >= 0) atomicAdd(&g_vt[cur * 64 + f], acc);
            cur = b; acc = v;
        } else acc += v;
    }
    if (cur >= 0) atomicAdd(&g_vt[cur * 64 + f], acc);
}

// ---- out = (vt/clip(cnt,1) - mu)*rstd*gamma + beta -----------------------
__global__ void k_final(float* __restrict__ out,
                        const float* __restrict__ gamma,
                        const float* __restrict__ beta) {
    int i = blockIdx.x * blockDim.x + threadIdx.x;
    if (i >= GG * HD) return;
    int g = i >> 6, f = i & 63;
    float mu = g_sum[f] * (1.f / NN);
    float var = g_sq[f] * (1.f / NN) - mu * mu;
    float rstd = rsqrtf(var + EPS_BN);
    float c = fmaxf(g_cnt[g], 1.f);
    out[i] = (g_vt[i] / c - mu) * rstd * __ldg(&gamma[f]) + __ldg(&beta[f]);
}

// =========================================================================
extern "C" void kernel_launch(void* const* d_in, const int* in_sizes, int n_in,
                              void* d_out, int out_size) {
    const float* atab  = (const float*)d_in[0];
    const float* btab  = (const float*)d_in[1];
    const float* vn0   = (const float*)d_in[2];
    const float* gcnW  = (const float*)d_in[3];
    const float* gcnb  = (const float*)d_in[4];
    const float* ngam  = (const float*)d_in[5];
    const float* nbet  = (const float*)d_in[6];
    const float* vnW1  = (const float*)d_in[7];
    const float* vnb1  = (const float*)d_in[8];
    const float* vng1  = (const float*)d_in[9];
    const float* vnbe1 = (const float*)d_in[10];
    const float* vnW2  = (const float*)d_in[11];
    const float* vnb2  = (const float*)d_in[12];
    const float* vng2  = (const float*)d_in[13];
    const float* vnbe2 = (const float*)d_in[14];
    const int*   x     = (const int*)d_in[15];
    const int*   ei    = (const int*)d_in[16];
    const int*   ea    = (const int*)d_in[17];
    const int*   batch = (const int*)d_in[18];
    float* out = (float*)d_out;

    const int MM_BLOCKS = (NN + 63) / 64;          // 1563
    const int BN_BLOCKS = (NN + 1023) / 1024;      // 98
    const int E_BLOCKS  = (EE + 255) / 256;        // 3907

    // init + CSR build (integer atomics only)
    k_init<<<(NN + 255) / 256, 256>>>(vn0);
    k_cnt<<<(NN + 32 * 256 - 1) / (32 * 256), 256>>>(batch);
    k_atom<<<(NN * 16 + 255) / 256, 256>>>((const float4*)atab, x, (const float4*)vn0);
    k_hist<<<E_BLOCKS, 256>>>(ei);
    k_scan1<<<BN_BLOCKS, 1024>>>();
    k_scan2<<<1, 128>>>();
    k_scan3<<<BN_BLOCKS, 1024>>>();
    k_fill<<<E_BLOCKS, 256>>>(ei, ea);

    // layer 0: conv only (reads g_h)
    k_gather<<<GATHER_BLOCKS, 256>>>(0, (const float2*)btab);
    k_matmul<<<MM_BLOCKS, 256>>>(1, gcnW, gcnb);

    // layers 1..6: BN->ReLU->vnode->conv->+res
    for (int l = 1; l < 7; l++) {
        int li = l - 1;
        k_bn_apply<<<BN_BLOCKS, 256>>>(ngam + li * 64, nbet + li * 64, batch);
        k_vn_a<<<GG, 64>>>(vnW1 + li * 4096, vnb1 + li * 64);
        k_vn_b<<<GG, 64>>>(vng1 + li * 64, vnbe1 + li * 64,
                           vnW2 + li * 4096, vnb2 + li * 64);
        k_vn_c<<<(GG * HD + 255) / 256, 256>>>(vng2 + li * 64, vnbe2 + li * 64);
        k_add_vn<<<(NN * HD + 255) / 256, 256>>>(batch);
        k_gather<<<GATHER_BLOCKS, 256>>>(1, (const float2*)btab);
        k_matmul<<<MM_BLOCKS, 256>>>(0, gcnW + l * 4096, gcnb + l * 64);
    }

    // readout: BN(h) then mean pool (BN is affine -> apply to pooled mean)
    k_pool<<<BN_BLOCKS, 256>>>(batch);
    k_final<<<(GG * HD + 255) / 256, 256>>>(out, ngam + 6 * 64, nbet + 6 * 64);
}

// round 10
// speedup vs baseline: 1.8839x; 1.6487x over previous
#include <cuda_runtime.h>

#define NN 100000      // nodes
#define EE 1000000     // edges
#define HD 64          // hidden
#define GG 512         // graphs
#define EPS_GEN 1e-7f
#define EPS_BN  1e-5f

// ---------------- scratch (device globals; no allocations) ----------------
__device__ float g_h [NN * HD];
__device__ float g_h2[NN * HD];
__device__ float g_m [NN * HD];   // conv input: h_in + aggregated messages
__device__ float g_vt[GG * HD];
__device__ float g_vn[GG * HD];
__device__ float g_sum[HD];
__device__ float g_sq [HD];
__device__ float g_ga[HD];        // node-BN scale  (gamma * rstd)
__device__ float g_sh[HD];        // node-BN shift  (beta - mu*ga)
__device__ float g_vnsA[2 * HD];
__device__ float g_vnsB[2 * HD];
__device__ float g_cnt[GG];
// CSR by destination
__device__ int g_deg[NN];
__device__ int g_rowptr[NN];
__device__ int g_cur[NN];
__device__ int g_bsum[128];
__device__ int g_boff[128];
__device__ unsigned g_epk[EE];    // packed: src | a0<<17 | a1<<20 | a2<<23

// ---------------- init: deg=0, cnt=0, vt=0, vn=vn0, stats=0 ---------------
__global__ void k_init(const float* __restrict__ vn0) {
    int i = blockIdx.x * blockDim.x + threadIdx.x;
    int stride = gridDim.x * blockDim.x;
    for (int j = i; j < NN; j += stride) g_deg[j] = 0;
    if (i < GG) g_cnt[i] = 0.f;
    if (i < GG * HD) { g_vn[i] = vn0[i & 63]; g_vt[i] = 0.f; }
    if (i < HD) { g_sum[i] = 0.f; g_sq[i] = 0.f; }
}

// ---------------- node counts per graph (run-length, batch sorted) --------
__global__ void k_cnt(const int* __restrict__ batch) {
    int t = blockIdx.x * blockDim.x + threadIdx.x;
    int base = t * 32;
    if (base >= NN) return;
    int end = min(base + 32, NN);
    int cur = batch[base];
    float acc = 0.f;
    for (int r = base; r < end; r++) {
        int b = batch[r];
        if (b != cur) { atomicAdd(&g_cnt[cur], acc); cur = b; acc = 0.f; }
        acc += 1.f;
    }
    atomicAdd(&g_cnt[cur], acc);
}

// ---------------- atom encoder: h = sum_f atom_table[x+off] + vn0 ---------
__global__ void k_atom(const float4* __restrict__ atab,
                       const int* __restrict__ x,
                       const float4* __restrict__ vn0) {
    int t = blockIdx.x * blockDim.x + threadIdx.x;
    int n = t >> 4, lane = t & 15;
    if (n >= NN) return;
    const int aoff[9] = {0, 119, 124, 136, 148, 158, 164, 170, 172};
    float4 a = __ldg(&vn0[lane]);
#pragma unroll
    for (int i = 0; i < 9; i++) {
        int idx = __ldg(&x[n * 9 + i]) + aoff[i];
        float4 v = __ldg(&atab[idx * 16 + lane]);
        a.x += v.x; a.y += v.y; a.z += v.z; a.w += v.w;
    }
    ((float4*)g_h)[n * 16 + lane] = a;
}

// ================= CSR build (per call; edges static within call) =========
__global__ void k_hist(const int* __restrict__ ei) {
    int e = blockIdx.x * 256 + threadIdx.x;
    if (e >= EE) return;
    atomicAdd(&g_deg[__ldg(&ei[EE + e])], 1);
}

__global__ void k_scan1() {   // 98 blocks x 1024: chunk sums
    __shared__ int ws[32];
    int b = blockIdx.x, tid = threadIdx.x;
    int i = b * 1024 + tid;
    int v = (i < NN) ? g_deg[i] : 0;
    int s = v;
#pragma unroll
    for (int o = 16; o; o >>= 1) s += __shfl_down_sync(~0u, s, o);
    if ((tid & 31) == 0) ws[tid >> 5] = s;
    __syncthreads();
    if (tid < 32) {
        int t = ws[tid];
#pragma unroll
        for (int o = 16; o; o >>= 1) t += __shfl_down_sync(~0u, t, o);
        if (tid == 0) g_bsum[b] = t;
    }
}

__global__ void k_scan2() {   // 1 block x 128: exclusive scan of chunk sums
    __shared__ int sm[128];
    int tid = threadIdx.x;
    int nb = (NN + 1023) / 1024;
    int v = (tid < nb) ? g_bsum[tid] : 0;
    sm[tid] = v; __syncthreads();
    for (int o = 1; o < 128; o <<= 1) {
        int t = (tid >= o) ? sm[tid - o] : 0;
        __syncthreads();
        sm[tid] += t;
        __syncthreads();
    }
    g_boff[tid] = sm[tid] - v;
}

__global__ void k_scan3() {   // 98 blocks x 1024: rowptr + cursor
    __shared__ int sm[1024];
    int b = blockIdx.x, tid = threadIdx.x;
    int i = b * 1024 + tid;
    int v = (i < NN) ? g_deg[i] : 0;
    sm[tid] = v; __syncthreads();
    for (int o = 1; o < 1024; o <<= 1) {
        int t = (tid >= o) ? sm[tid - o] : 0;
        __syncthreads();
        sm[tid] += t;
        __syncthreads();
    }
    if (i < NN) {
        int r = g_boff[b] + sm[tid] - v;   // exclusive
        g_rowptr[i] = r;
        g_cur[i] = r;
    }
}

__global__ void k_fill(const int* __restrict__ ei, const int* __restrict__ ea) {
    int e = blockIdx.x * 256 + threadIdx.x;
    if (e >= EE) return;
    int dst = __ldg(&ei[EE + e]);
    int p = atomicAdd(&g_cur[dst], 1);
    unsigned pk = (unsigned)__ldg(&ei[e])
                | ((unsigned)__ldg(&ea[e * 3 + 0]) << 17)
                | ((unsigned)__ldg(&ea[e * 3 + 1]) << 20)
                | ((unsigned)__ldg(&ea[e * 3 + 2]) << 23);
    g_epk[p] = pk;
}

// ====== gather: g_m[n] = hin[n] + sum_e relu(hin[src]+bond_emb)+eps =======
// half-warp (16 lanes, float4) per node -> 2 nodes per warp, MLP doubled
#define GATHER_BLOCKS 3125
__global__ void __launch_bounds__(256) k_gather(int use_h2,
                                                const float4* __restrict__ btab4) {
    __shared__ float4 comb[960];   // 60 combos x 16 float4 = 15KB
    int tid = threadIdx.x;
    for (int i = tid; i < 960; i += 256) {
        int c = i >> 4, f = i & 15;
        int a0 = c % 5, t = c / 5, a1 = t % 6, a2 = t / 6;
        float4 v0 = __ldg(&btab4[a0 * 16 + f]);
        float4 v1 = __ldg(&btab4[(5 + a1) * 16 + f]);
        float4 v2 = __ldg(&btab4[(11 + a2) * 16 + f]);
        comb[i] = make_float4(v0.x + v1.x + v2.x, v0.y + v1.y + v2.y,
                              v0.z + v1.z + v2.z, v0.w + v1.w + v2.w);
    }
    __syncthreads();

    const float4* __restrict__ hin =
        use_h2 ? (const float4*)g_h2 : (const float4*)g_h;

    int lane = tid & 15;         // feature quad
    int sub  = tid >> 4;         // 16 half-warps per block
    for (int n = blockIdx.x * 16 + sub; n < NN; n += GATHER_BLOCKS * 16) {
        int start = __ldg(&g_rowptr[n]);
        int deg   = __ldg(&g_deg[n]);
        float4 acc = __ldg(&hin[n * 16 + lane]);
        int j = 0;
        for (; j + 4 <= deg; j += 4) {
            unsigned pk[4];
            float4 hv[4];
#pragma unroll
            for (int t = 0; t < 4; t++) pk[t] = __ldg(&g_epk[start + j + t]);
#pragma unroll
            for (int t = 0; t < 4; t++)
                hv[t] = __ldg(&hin[(pk[t] & 0x1FFFF) * 16 + lane]);
#pragma unroll
            for (int t = 0; t < 4; t++) {
                int c = ((pk[t] >> 17) & 7) + 5 * ((pk[t] >> 20) & 7)
                      + 30 * ((pk[t] >> 23) & 1);
                float4 e = comb[c * 16 + lane];
                acc.x += fmaxf(hv[t].x + e.x, 0.f) + EPS_GEN;
                acc.y += fmaxf(hv[t].y + e.y, 0.f) + EPS_GEN;
                acc.z += fmaxf(hv[t].z + e.z, 0.f) + EPS_GEN;
                acc.w += fmaxf(hv[t].w + e.w, 0.f) + EPS_GEN;
            }
        }
        for (; j < deg; j++) {
            unsigned p = __ldg(&g_epk[start + j]);
            float4 h = __ldg(&hin[(p & 0x1FFFF) * 16 + lane]);
            int c = ((p >> 17) & 7) + 5 * ((p >> 20) & 7) + 30 * ((p >> 23) & 1);
            float4 e = comb[c * 16 + lane];
            acc.x += fmaxf(h.x + e.x, 0.f) + EPS_GEN;
            acc.y += fmaxf(h.y + e.y, 0.f) + EPS_GEN;
            acc.z += fmaxf(h.z + e.z, 0.f) + EPS_GEN;
            acc.w += fmaxf(h.w + e.w, 0.f) + EPS_GEN;
        }
        ((float4*)g_m)[n * 16 + lane] = acc;
    }
}

// ---------------- g_m @ W + b (+res) -> g_h ; fused BN stats --------------
__global__ void __launch_bounds__(256) k_matmul(int layer0,
                                                const float* __restrict__ W,
                                                const float* __restrict__ bias) {
    __shared__ __align__(16) float W_sh[64 * 64];
    __shared__ float in_sh[64][65];
    __shared__ float s_sum[64], s_sq[64];
    int tid = threadIdx.x;
    int base = blockIdx.x * 64;
    {
        const float4* W4 = (const float4*)W;
        float4* Ws4 = (float4*)W_sh;
#pragma unroll
        for (int i = 0; i < 4; i++) Ws4[tid + i * 256] = __ldg(&W4[tid + i * 256]);
    }
#pragma unroll
    for (int i = 0; i < 16; i++) {
        int idx = tid + i * 256;
        int r = idx >> 6, f = idx & 63;
        int row = base + r;
        in_sh[r][f] = (row < NN) ? g_m[row * 64 + f] : 0.f;
    }
    if (tid < 64) { s_sum[tid] = 0.f; s_sq[tid] = 0.f; }
    __syncthreads();

    int ng = tid >> 4, cg = tid & 15;
    float acc[4][4];
#pragma unroll
    for (int i = 0; i < 4; i++)
#pragma unroll
        for (int j = 0; j < 4; j++) acc[i][j] = 0.f;
#pragma unroll 8
    for (int k = 0; k < 64; k++) {
        float4 w = *(const float4*)&W_sh[k * 64 + cg * 4];
#pragma unroll
        for (int i = 0; i < 4; i++) {
            float iv = in_sh[ng * 4 + i][k];
            acc[i][0] = fmaf(iv, w.x, acc[i][0]);
            acc[i][1] = fmaf(iv, w.y, acc[i][1]);
            acc[i][2] = fmaf(iv, w.z, acc[i][2]);
            acc[i][3] = fmaf(iv, w.w, acc[i][3]);
        }
    }
    float4 bv = __ldg((const float4*)bias + cg);
    float csum[4] = {0, 0, 0, 0}, csq[4] = {0, 0, 0, 0};
#pragma unroll
    for (int i = 0; i < 4; i++) {
        int row = base + ng * 4 + i;
        if (row < NN) {
            float4 o;
            o.x = acc[i][0] + bv.x; o.y = acc[i][1] + bv.y;
            o.z = acc[i][2] + bv.z; o.w = acc[i][3] + bv.w;
            if (!layer0) {
                float4 r = *((const float4*)g_h + row * 16 + cg);
                o.x += r.x; o.y += r.y; o.z += r.z; o.w += r.w;
            }
            *((float4*)g_h + row * 16 + cg) = o;
            csum[0] += o.x; csq[0] += o.x * o.x;
            csum[1] += o.y; csq[1] += o.y * o.y;
            csum[2] += o.z; csq[2] += o.z * o.z;
            csum[3] += o.w; csq[3] += o.w * o.w;
        }
    }
#pragma unroll
    for (int j = 0; j < 4; j++) {
        atomicAdd(&s_sum[cg * 4 + j], csum[j]);
        atomicAdd(&s_sq [cg * 4 + j], csq[j]);
    }
    __syncthreads();
    if (tid < 64) {
        atomicAdd(&g_sum[tid], s_sum[tid]);
        atomicAdd(&g_sq [tid], s_sq[tid]);
    }
}

// ---- pool relu(BN(h)) -> vt (read-only; no h2 write); zero vn stats ------
__global__ void __launch_bounds__(256) k_bn_pool(const float* __restrict__ gamma,
                                                 const float* __restrict__ beta,
                                                 const int* __restrict__ batch) {
    int tid = threadIdx.x;
    int f = tid & 63;
    float mu = g_sum[f] * (1.f / NN);
    float var = g_sq[f] * (1.f / NN) - mu * mu;
    float ga = gamma[f] * rsqrtf(var + EPS_BN);
    float sh = beta[f] - mu * ga;
    if (blockIdx.x == 0 && tid < 128) { g_vnsA[tid] = 0.f; g_vnsB[tid] = 0.f; }
    int base = blockIdx.x * 256;
    int r0 = base + (tid >> 6);
    int rend = min(base + 256, NN);
    int cur = -1;
    float acc = 0.f;
    for (int r = r0; r < rend; r += 4) {
        float v = fmaxf(fmaf(g_h[r * 64 + f], ga, sh), 0.f);
        int b = __ldg(&batch[r]);
        if (b != cur) {
            if (cur >= 0) atomicAdd(&g_vt[cur * 64 + f], acc);
            cur = b; acc = v;
        } else acc += v;
    }
    if (cur >= 0) atomicAdd(&g_vt[cur * 64 + f], acc);
}

// ---- virtual node MLP ----------------------------------------------------
__global__ void k_vn_a(const float* __restrict__ W1, const float* __restrict__ b1) {
    __shared__ float row[64];
    int g = blockIdx.x, j = threadIdx.x;
    row[j] = g_vt[g * 64 + j] + g_vn[g * 64 + j];
    __syncthreads();
    float acc = __ldg(&b1[j]);
#pragma unroll
    for (int k = 0; k < 64; k++) acc = fmaf(row[k], __ldg(&W1[k * 64 + j]), acc);
    g_vt[g * 64 + j] = acc;
    atomicAdd(&g_vnsA[j], acc);
    atomicAdd(&g_vnsA[64 + j], acc * acc);
}

__global__ void k_vn_b(const float* __restrict__ g1, const float* __restrict__ be1,
                       const float* __restrict__ W2, const float* __restrict__ b2) {
    __shared__ float z[64];
    int g = blockIdx.x, j = threadIdx.x;
    float mu = g_vnsA[j] * (1.f / GG);
    float var = g_vnsA[64 + j] * (1.f / GG) - mu * mu;
    float ga = __ldg(&g1[j]) * rsqrtf(var + EPS_BN);
    float y = g_vt[g * 64 + j];
    z[j] = fmaxf((y - mu) * ga + __ldg(&be1[j]), 0.f);
    __syncthreads();
    float acc = __ldg(&b2[j]);
#pragma unroll
    for (int k = 0; k < 64; k++) acc = fmaf(z[k], __ldg(&W2[k * 64 + j]), acc);
    g_vt[g * 64 + j] = acc;
    atomicAdd(&g_vnsB[j], acc);
    atomicAdd(&g_vnsB[64 + j], acc * acc);
}

// ---- vn = relu(BN2(y2)); also precompute node-BN coeffs ga/sh ------------
__global__ void k_vn_c(const float* __restrict__ g2, const float* __restrict__ be2,
                       const float* __restrict__ gamma, const float* __restrict__ beta) {
    int i = blockIdx.x * blockDim.x + threadIdx.x;
    if (i < HD) {   // node-BN coefficients for k_h2
        float mu = g_sum[i] * (1.f / NN);
        float var = g_sq[i] * (1.f / NN) - mu * mu;
        float ga = gamma[i] * rsqrtf(var + EPS_BN);
        g_ga[i] = ga;
        g_sh[i] = beta[i] - mu * ga;
    }
    if (i >= GG * HD) return;
    int j = i & 63;
    float mu = g_vnsB[j] * (1.f / GG);
    float var = g_vnsB[64 + j] * (1.f / GG) - mu * mu;
    float ga = __ldg(&g2[j]) * rsqrtf(var + EPS_BN);
    g_vn[i] = fmaxf((g_vt[i] - mu) * ga + __ldg(&be2[j]), 0.f);
}

// ---- h2 = relu(BN(h)) + vn[batch]; zero node stats + vt ------------------
__global__ void __launch_bounds__(256) k_h2(const int* __restrict__ batch) {
    int idx = blockIdx.x * 256 + threadIdx.x;   // float4 index
    if (blockIdx.x == 0 && threadIdx.x < 64) {
        g_sum[threadIdx.x] = 0.f;
        g_sq[threadIdx.x] = 0.f;
    }
    if (blockIdx.x == 1) {
        for (int i = threadIdx.x; i < GG * HD; i += 256) g_vt[i] = 0.f;
    }
    if (idx >= NN * 16) return;
    int n = idx >> 4, fq = idx & 15;
    int b = __ldg(&batch[n]);
    float4 h = ((const float4*)g_h)[idx];
    float4 vn = __ldg((const float4*)g_vn + b * 16 + fq);
    float4 ga = *((const float4*)g_ga + fq);
    float4 sh = *((const float4*)g_sh + fq);
    float4 o;
    o.x = fmaxf(fmaf(h.x, ga.x, sh.x), 0.f) + vn.x;
    o.y = fmaxf(fmaf(h.y, ga.y, sh.y), 0.f) + vn.y;
    o.z = fmaxf(fmaf(h.z, ga.z, sh.z), 0.f) + vn.z;
    o.w = fmaxf(fmaf(h.w, ga.w, sh.w), 0.f) + vn.w;
    ((float4*)g_h2)[idx] = o;
}

// ---- pool: vt[g] = segment_sum(h) (raw h; final readout) -----------------
__global__ void __launch_bounds__(256) k_pool(const int* __restrict__ batch) {
    int tid = threadIdx.x;
    int f = tid & 63;
    int base = blockIdx.x * 256;
    int r0 = base + (tid >> 6);
    int rend = min(base + 256, NN);
    int cur = -1;
    float acc = 0.f;
    for (int r = r0; r < rend; r += 4) {
        float v = g_h[r * 64 + f];
        int b = __ldg(&batch[r]);
        if (b != cur) {
            if (cur >= 0) atomicAdd(&g_vt[cur * 64 + f], acc);
            cur = b; acc = v;
        } else acc += v;
    }
    if (cur >= 0) atomicAdd(&g_vt[cur * 64 + f], acc);
}

// ---- out = (vt/clip(cnt,1) - mu)*rstd*gamma + beta -----------------------
__global__ void k_final(float* __restrict__ out,
                        const float* __restrict__ gamma,
                        const float* __restrict__ beta) {
    int i = blockIdx.x * blockDim.x + threadIdx.x;
    if (i >= GG * HD) return;
    int g = i >> 6, f = i & 63;
    float mu = g_sum[f] * (1.f / NN);
    float var = g_sq[f] * (1.f / NN) - mu * mu;
    float rstd = rsqrtf(var + EPS_BN);
    float c = fmaxf(g_cnt[g], 1.f);
    out[i] = (g_vt[i] / c - mu) * rstd * __ldg(&gamma[f]) + __ldg(&beta[f]);
}

// =========================================================================
extern "C" void kernel_launch(void* const* d_in, const int* in_sizes, int n_in,
                              void* d_out, int out_size) {
    const float* atab  = (const float*)d_in[0];
    const float* btab  = (const float*)d_in[1];
    const float* vn0   = (const float*)d_in[2];
    const float* gcnW  = (const float*)d_in[3];
    const float* gcnb  = (const float*)d_in[4];
    const float* ngam  = (const float*)d_in[5];
    const float* nbet  = (const float*)d_in[6];
    const float* vnW1  = (const float*)d_in[7];
    const float* vnb1  = (const float*)d_in[8];
    const float* vng1  = (const float*)d_in[9];
    const float* vnbe1 = (const float*)d_in[10];
    const float* vnW2  = (const float*)d_in[11];
    const float* vnb2  = (const float*)d_in[12];
    const float* vng2  = (const float*)d_in[13];
    const float* vnbe2 = (const float*)d_in[14];
    const int*   x     = (const int*)d_in[15];
    const int*   ei    = (const int*)d_in[16];
    const int*   ea    = (const int*)d_in[17];
    const int*   batch = (const int*)d_in[18];
    float* out = (float*)d_out;

    const int MM_BLOCKS = (NN + 63) / 64;          // 1563
    const int SC_BLOCKS = (NN + 1023) / 1024;      // 98  (scans)
    const int PL_BLOCKS = (NN + 255) / 256;        // 391 (pool passes)
    const int E_BLOCKS  = (EE + 255) / 256;        // 3907
    const int H2_BLOCKS = (NN * 16 + 255) / 256;   // 6250

    // init + CSR build (integer atomics only)
    k_init<<<(NN + 255) / 256, 256>>>(vn0);
    k_cnt<<<(NN + 32 * 256 - 1) / (32 * 256), 256>>>(batch);
    k_atom<<<(NN * 16 + 255) / 256, 256>>>((const float4*)atab, x, (const float4*)vn0);
    k_hist<<<E_BLOCKS, 256>>>(ei);
    k_scan1<<<SC_BLOCKS, 1024>>>();
    k_scan2<<<1, 128>>>();
    k_scan3<<<SC_BLOCKS, 1024>>>();
    k_fill<<<E_BLOCKS, 256>>>(ei, ea);

    // layer 0: conv only (reads g_h)
    k_gather<<<GATHER_BLOCKS, 256>>>(0, (const float4*)btab);
    k_matmul<<<MM_BLOCKS, 256>>>(1, gcnW, gcnb);

    // layers 1..6: BN->ReLU->vnode->conv->+res
    for (int l = 1; l < 7; l++) {
        int li = l - 1;
        k_bn_pool<<<PL_BLOCKS, 256>>>(ngam + li * 64, nbet + li * 64, batch);
        k_vn_a<<<GG, 64>>>(vnW1 + li * 4096, vnb1 + li * 64);
        k_vn_b<<<GG, 64>>>(vng1 + li * 64, vnbe1 + li * 64,
                           vnW2 + li * 4096, vnb2 + li * 64);
        k_vn_c<<<(GG * HD + 255) / 256, 256>>>(vng2 + li * 64, vnbe2 + li * 64,
                                               ngam + li * 64, nbet + li * 64);
        k_h2<<<H2_BLOCKS, 256>>>(batch);
        k_gather<<<GATHER_BLOCKS, 256>>>(1, (const float4*)btab);
        k_matmul<<<MM_BLOCKS, 256>>>(0, gcnW + l * 4096, gcnb + l * 64);
    }

    // readout: mean pool of h, BN applied as affine on pooled mean
    k_pool<<<PL_BLOCKS, 256>>>(batch);
    k_final<<<(GG * HD + 255) / 256, 256>>>(out, ngam + 6 * 64, nbet + 6 * 64);
}